// round 11
// baseline (speedup 1.0000x reference)
#include <cuda_runtime.h>
#include <cuda_bf16.h>
#include <cuda_fp16.h>
#include <stdint.h>

#define NMAX   100000
#define EMAX   1600000
#define CINC   128
#define COUTC  64
#define CAP    96     // per-vertex slot capacity; overflow -> g_ov fixup (statistically never)

// ---------------- static device scratch (no allocation) ----------------
__device__ int     g_cur[NMAX];                     // slot cursor == in-degree after bucketing
__device__ float   g_dinv[NMAX];                    // rsqrt(1+deg)
__device__ float   g_H[(size_t)NMAX * COUTC];       // H fp32 (self term, overflow path)
__device__ uint4   g_Hh[(size_t)NMAX * (COUTC/8)];  // H fp16 copy, 16B-aligned (edge gather)
__device__ int     g_entry[(size_t)NMAX * CAP];     // per-dst src lists (38.4 MB)
__device__ int     g_ov[EMAX];                      // overflow edge indices
__device__ int     g_ovcnt;

// ---------------- K1: zero counters ----------------
__global__ void __launch_bounds__(256) k_zero(int n) {
    int i = blockIdx.x * blockDim.x + threadIdx.x;
    if (i < n) g_cur[i] = 0;
    if (i == 0) g_ovcnt = 0;
}

// ---------------- K2: bucket edges by dst (also produces in-degree) ----------------
__global__ void __launch_bounds__(256) k_scatter(const int* __restrict__ src,
                                                 const int* __restrict__ dst, int E) {
    int e = blockIdx.x * blockDim.x + threadIdx.x;
    if (e >= E) return;
    int s = src[e], d = dst[e];
    int pos = atomicAdd(&g_cur[d], 1);
    if (pos < CAP) {
        g_entry[(size_t)d * CAP + pos] = s;
    } else {
        int o = atomicAdd(&g_ovcnt, 1);
        g_ov[o] = e;
    }
}

// ---------------- K3: dinv = rsqrt(1+deg) ----------------
__global__ void __launch_bounds__(256) k_dinv(int n) {
    int i = blockIdx.x * blockDim.x + threadIdx.x;
    if (i < n) g_dinv[i] = rsqrtf(1.0f + (float)g_cur[i]);
}

// ---------------- K4: GEMM H = X@W + b  (writes fp32 + fp16 copies) ----------------
// 128 threads, 128x64 tile, 8x8 microtile, Xs transposed (k-major) so A and B
// fragments both load via LDS.128. 64 B LDS per 64 FMAs per thread per k.
#define BM 128
#define BN 64
#define BK 32
#define XS_LD (BM + 4)   // 132, padded
__global__ void __launch_bounds__(128) k_gemm(const float* __restrict__ X,
                                              const float* __restrict__ W,
                                              const float* __restrict__ b, int N) {
    __shared__ float Xs[BK * XS_LD];   // [k][row], padded
    __shared__ float Ws[BK * BN];      // [k][col]

    int tid = threadIdx.x;
    int rowBase = blockIdx.x * BM;
    int tx = tid & 7;        // 8 col-groups of 8 cols
    int ty = tid >> 3;       // 16 row-groups of 8 rows
    int r0 = ty * 8, c0 = tx * 8;

    float acc[8][8] = {};

    for (int kc = 0; kc < CINC; kc += BK) {
        // stage W chunk [BK][BN]: 512 float4, 4 per thread
#pragma unroll
        for (int j = 0; j < 4; j++) {
            int i4 = tid + j * 128;
            int k = i4 >> 4, c4 = (i4 & 15) * 4;
            *reinterpret_cast<float4*>(&Ws[k * BN + c4]) =
                *reinterpret_cast<const float4*>(&W[(size_t)(kc + k) * COUTC + c4]);
        }
        // stage X chunk transposed: 128 rows x 32 k
#pragma unroll
        for (int j = 0; j < 8; j++) {
            int i4 = tid + j * 128;
            int r = i4 >> 3;            // 0..127
            int kq = (i4 & 7) * 4;      // 0,4,...,28
            int gr = rowBase + r;
            float4 v = make_float4(0.f, 0.f, 0.f, 0.f);
            if (gr < N) v = *reinterpret_cast<const float4*>(&X[(size_t)gr * CINC + kc + kq]);
            Xs[(kq + 0) * XS_LD + r] = v.x;
            Xs[(kq + 1) * XS_LD + r] = v.y;
            Xs[(kq + 2) * XS_LD + r] = v.z;
            Xs[(kq + 3) * XS_LD + r] = v.w;
        }
        __syncthreads();

#pragma unroll
        for (int k = 0; k < BK; k++) {
            float4 a0 = *reinterpret_cast<const float4*>(&Xs[k * XS_LD + r0]);
            float4 a1 = *reinterpret_cast<const float4*>(&Xs[k * XS_LD + r0 + 4]);
            float4 w0 = *reinterpret_cast<const float4*>(&Ws[k * BN + c0]);
            float4 w1 = *reinterpret_cast<const float4*>(&Ws[k * BN + c0 + 4]);
            float a[8] = {a0.x, a0.y, a0.z, a0.w, a1.x, a1.y, a1.z, a1.w};
            float w[8] = {w0.x, w0.y, w0.z, w0.w, w1.x, w1.y, w1.z, w1.w};
#pragma unroll
            for (int i = 0; i < 8; i++)
#pragma unroll
                for (int j = 0; j < 8; j++)
                    acc[i][j] = fmaf(a[i], w[j], acc[i][j]);
        }
        __syncthreads();
    }

    float4 bv0 = *reinterpret_cast<const float4*>(&b[c0]);
    float4 bv1 = *reinterpret_cast<const float4*>(&b[c0 + 4]);
#pragma unroll
    for (int i = 0; i < 8; i++) {
        int row = rowBase + r0 + i;
        if (row >= N) break;
        float4 h0, h1;
        h0.x = acc[i][0] + bv0.x; h0.y = acc[i][1] + bv0.y;
        h0.z = acc[i][2] + bv0.z; h0.w = acc[i][3] + bv0.w;
        h1.x = acc[i][4] + bv1.x; h1.y = acc[i][5] + bv1.y;
        h1.z = acc[i][6] + bv1.z; h1.w = acc[i][7] + bv1.w;
        *reinterpret_cast<float4*>(&g_H[(size_t)row * COUTC + c0])     = h0;
        *reinterpret_cast<float4*>(&g_H[(size_t)row * COUTC + c0 + 4]) = h1;

        __half2 p0 = __floats2half2_rn(h0.x, h0.y);
        __half2 p1 = __floats2half2_rn(h0.z, h0.w);
        __half2 p2 = __floats2half2_rn(h1.x, h1.y);
        __half2 p3 = __floats2half2_rn(h1.z, h1.w);
        uint4 pk;
        pk.x = *reinterpret_cast<uint32_t*>(&p0);
        pk.y = *reinterpret_cast<uint32_t*>(&p1);
        pk.z = *reinterpret_cast<uint32_t*>(&p2);
        pk.w = *reinterpret_cast<uint32_t*>(&p3);
        g_Hh[(size_t)row * (COUTC/8) + (c0 >> 3)] = pk;   // c0 in {0,8,...,56} -> slot 0..7
    }
}

// ---------------- K5: warp-per-vertex pull gather (fp16 H) + fp32 self term + ReLU ----------------
__global__ void __launch_bounds__(256) k_gather(float* __restrict__ out, int N) {
    int w = (blockIdx.x * blockDim.x + threadIdx.x) >> 5;
    int lane = threadIdx.x & 31;
    if (w >= N) return;

    int cnt = g_cur[w];
    if (cnt > CAP) cnt = CAP;
    float dw = g_dinv[w];
    const int* ep = &g_entry[(size_t)w * CAP];

    // lane-parallel prefetch of up to 32 (src, coef) pairs in one coalesced shot
    int   sl = 0;
    float cl = 0.0f;
    if (lane < cnt) {
        sl = ep[lane];
        cl = g_dinv[sl] * dw;
    }
    int m = cnt < 32 ? cnt : 32;

    const __half2* Hh = reinterpret_cast<const __half2*>(g_Hh);

    float2 acc = make_float2(0.0f, 0.0f);
#pragma unroll 4
    for (int i = 0; i < m; i++) {
        int   s  = __shfl_sync(0xffffffffu, sl, i);
        float cf = __shfl_sync(0xffffffffu, cl, i);
        float2 h = __half22float2(Hh[(size_t)s * (COUTC/2) + lane]);
        acc.x = fmaf(h.x, cf, acc.x);
        acc.y = fmaf(h.y, cf, acc.y);
    }
    // rare tail: deg > 32
    for (int i = 32; i < cnt; i++) {
        int s = ep[i];
        float cf = g_dinv[s] * dw;
        float2 h = __half22float2(Hh[(size_t)s * (COUTC/2) + lane]);
        acc.x = fmaf(h.x, cf, acc.x);
        acc.y = fmaf(h.y, cf, acc.y);
    }

    // self-loop term in fp32
    int c = lane * 2;
    float2 hw = *reinterpret_cast<const float2*>(&g_H[(size_t)w * COUTC + c]);
    float d2 = dw * dw;
    float2 o;
    o.x = fmaf(hw.x, d2, acc.x);
    o.y = fmaf(hw.y, d2, acc.y);

    if (g_ovcnt == 0) {           // normal path: fuse ReLU here
        o.x = fmaxf(o.x, 0.0f);
        o.y = fmaxf(o.y, 0.0f);
    }
    *reinterpret_cast<float2*>(&out[(size_t)w * COUTC + c]) = o;
}

// ---------------- K6: overflow fixup (no-op when g_ovcnt == 0) ----------------
__global__ void __launch_bounds__(256) k_overflow(const int* __restrict__ src,
                                                  const int* __restrict__ dst,
                                                  float* __restrict__ out) {
    int total = g_ovcnt;
    for (int i = blockIdx.x * blockDim.x + threadIdx.x; i < total;
         i += gridDim.x * blockDim.x) {
        int e = g_ov[i];
        int s = src[e], d = dst[e];
        float cf = g_dinv[s] * g_dinv[d];
        const float* hp = &g_H[(size_t)s * COUTC];
        float* op = &out[(size_t)d * COUTC];
#pragma unroll
        for (int ch = 0; ch < COUTC; ch++) atomicAdd(&op[ch], hp[ch] * cf);
    }
}

// ---------------- K7: deferred ReLU (no-op when g_ovcnt == 0) ----------------
__global__ void __launch_bounds__(256) k_relufix(float* __restrict__ out, int total) {
    if (g_ovcnt == 0) return;
    for (int i = blockIdx.x * blockDim.x + threadIdx.x; i < total;
         i += gridDim.x * blockDim.x) {
        out[i] = fmaxf(out[i], 0.0f);
    }
}

// ---------------- launch ----------------
extern "C" void kernel_launch(void* const* d_in, const int* in_sizes, int n_in,
                              void* d_out, int out_size) {
    const float* X   = (const float*)d_in[0];
    const float* W   = (const float*)d_in[1];
    const float* b   = (const float*)d_in[2];
    const int*   src = (const int*)d_in[3];
    const int*   dst = (const int*)d_in[4];
    float* out = (float*)d_out;

    int N = in_sizes[0] / CINC;
    int E = in_sizes[3];

    k_zero<<<(N + 255) / 256, 256>>>(N);
    k_scatter<<<(E + 255) / 256, 256>>>(src, dst, E);
    k_dinv<<<(N + 255) / 256, 256>>>(N);
    k_gemm<<<(N + BM - 1) / BM, 128>>>(X, W, b, N);
    k_gather<<<(int)(((long long)N * 32 + 255) / 256), 256>>>(out, N);
    k_overflow<<<148, 256>>>(src, dst, out);
    k_relufix<<<296, 256>>>(out, N * COUTC);
}

// round 17
// speedup vs baseline: 1.0563x; 1.0563x over previous
#include <cuda_runtime.h>
#include <cuda_bf16.h>
#include <cuda_fp16.h>
#include <stdint.h>

#define NMAX   100000
#define EMAX   1600000
#define CINC   128
#define COUTC  64
#define CAP    96

// ---------------- static device scratch (zero-initialized at load; cleanup kernel
// restores the all-zero invariant at the end of every launch) ----------------
__device__ int     g_cur[NMAX];                     // slot cursor == in-degree
__device__ float   g_H[(size_t)NMAX * COUTC];       // H fp32 (self term, overflow)
__device__ uint4   g_Hh[(size_t)NMAX * (COUTC/8)];  // H fp16 copy (edge gather)
__device__ int     g_entry[(size_t)NMAX * CAP];
__device__ int     g_ov[EMAX];
__device__ int     g_ovcnt;

// ---------------- K1: fused GEMM + edge bucketing (independent work, complementary pipes) ----------------
// Blocks [0, gemmBlocks): R3-measured GEMM (64x64 tile, 4x4 microtile, 256 thr, 34KB smem)
// Blocks [gemmBlocks, ...): scatter 256 edges/block
__global__ void __launch_bounds__(256) k_fused(const float* __restrict__ X,
                                               const float* __restrict__ W,
                                               const float* __restrict__ b,
                                               const int* __restrict__ src,
                                               const int* __restrict__ dst,
                                               int N, int E, int gemmBlocks) {
    int tid = threadIdx.x;
    if (blockIdx.x < gemmBlocks) {
        // ---------- GEMM path ----------
        __shared__ float Xs[64 * 68];   // [row][k] padded
        __shared__ float Ws[64 * 64];   // [k][col]

        int rowBase = blockIdx.x * 64;
        int tx = tid & 15, ty = tid >> 4;       // 16x16 threads
        int r0 = ty * 4, c0 = tx * 4;           // 4x4 microtile
        float acc[4][4] = {};

        for (int kc = 0; kc < CINC; kc += 64) {
            for (int i4 = tid; i4 < 1024; i4 += 256) {          // W chunk 64k x 64c
                int k = i4 >> 4, c4 = (i4 & 15) * 4;
                *reinterpret_cast<float4*>(&Ws[k * 64 + c4]) =
                    *reinterpret_cast<const float4*>(&W[(size_t)(kc + k) * COUTC + c4]);
            }
            for (int i4 = tid; i4 < 1024; i4 += 256) {          // X chunk 64r x 64k
                int r = i4 >> 4, k4 = (i4 & 15) * 4;
                int gr = rowBase + r;
                float4 v = make_float4(0.f, 0.f, 0.f, 0.f);
                if (gr < N) v = *reinterpret_cast<const float4*>(&X[(size_t)gr * CINC + kc + k4]);
                *reinterpret_cast<float4*>(&Xs[r * 68 + k4]) = v;
            }
            __syncthreads();

#pragma unroll 8
            for (int k = 0; k < 64; k++) {
                float a0 = Xs[(r0 + 0) * 68 + k];
                float a1 = Xs[(r0 + 1) * 68 + k];
                float a2 = Xs[(r0 + 2) * 68 + k];
                float a3 = Xs[(r0 + 3) * 68 + k];
                float4 w4 = *reinterpret_cast<const float4*>(&Ws[k * 64 + c0]);
                acc[0][0] = fmaf(a0, w4.x, acc[0][0]); acc[0][1] = fmaf(a0, w4.y, acc[0][1]);
                acc[0][2] = fmaf(a0, w4.z, acc[0][2]); acc[0][3] = fmaf(a0, w4.w, acc[0][3]);
                acc[1][0] = fmaf(a1, w4.x, acc[1][0]); acc[1][1] = fmaf(a1, w4.y, acc[1][1]);
                acc[1][2] = fmaf(a1, w4.z, acc[1][2]); acc[1][3] = fmaf(a1, w4.w, acc[1][3]);
                acc[2][0] = fmaf(a2, w4.x, acc[2][0]); acc[2][1] = fmaf(a2, w4.y, acc[2][1]);
                acc[2][2] = fmaf(a2, w4.z, acc[2][2]); acc[2][3] = fmaf(a2, w4.w, acc[2][3]);
                acc[3][0] = fmaf(a3, w4.x, acc[3][0]); acc[3][1] = fmaf(a3, w4.y, acc[3][1]);
                acc[3][2] = fmaf(a3, w4.z, acc[3][2]); acc[3][3] = fmaf(a3, w4.w, acc[3][3]);
            }
            __syncthreads();
        }

        float4 bv = *reinterpret_cast<const float4*>(&b[c0]);
#pragma unroll
        for (int i = 0; i < 4; i++) {
            int row = rowBase + r0 + i;
            if (row >= N) break;
            float4 h;
            h.x = acc[i][0] + bv.x; h.y = acc[i][1] + bv.y;
            h.z = acc[i][2] + bv.z; h.w = acc[i][3] + bv.w;
            *reinterpret_cast<float4*>(&g_H[(size_t)row * COUTC + c0]) = h;
            // fp16 copy for the gather (R11-validated: rel_err ~2e-4)
            __half2 p0 = __floats2half2_rn(h.x, h.y);
            __half2 p1 = __floats2half2_rn(h.z, h.w);
            uint2 pk;
            pk.x = *reinterpret_cast<uint32_t*>(&p0);
            pk.y = *reinterpret_cast<uint32_t*>(&p1);
            *reinterpret_cast<uint2*>(reinterpret_cast<char*>(g_Hh) +
                                      (size_t)row * (COUTC * 2) + c0 * 2) = pk;
        }
    } else {
        // ---------- scatter path: bucket edges by dst ----------
        int e = (blockIdx.x - gemmBlocks) * 256 + tid;
        if (e >= E) return;
        int s = src[e], d = dst[e];
        int pos = atomicAdd(&g_cur[d], 1);
        if (pos < CAP) {
            g_entry[(size_t)d * CAP + pos] = s;
        } else {
            int o = atomicAdd(&g_ovcnt, 1);
            g_ov[o] = e;
        }
    }
}

// ---------------- K2: warp-per-vertex pull gather (fp16 H, inline rsqrt) + self + ReLU ----------------
__global__ void __launch_bounds__(256) k_gather(float* __restrict__ out, int N) {
    int w = (blockIdx.x * blockDim.x + threadIdx.x) >> 5;
    int lane = threadIdx.x & 31;
    if (w >= N) return;

    int cntw = g_cur[w];
    float dw = rsqrtf(1.0f + (float)cntw);
    int cnt = cntw > CAP ? CAP : cntw;
    const int* ep = &g_entry[(size_t)w * CAP];

    int   sl = 0;
    float cl = 0.0f;
    if (lane < cnt) {
        sl = ep[lane];
        cl = rsqrtf(1.0f + (float)g_cur[sl]) * dw;
    }
    int m = cnt < 32 ? cnt : 32;

    const __half2* Hh = reinterpret_cast<const __half2*>(g_Hh);

    float2 acc = make_float2(0.0f, 0.0f);
#pragma unroll 4
    for (int i = 0; i < m; i++) {
        int   s  = __shfl_sync(0xffffffffu, sl, i);
        float cf = __shfl_sync(0xffffffffu, cl, i);
        float2 h = __half22float2(Hh[(size_t)s * (COUTC / 2) + lane]);
        acc.x = fmaf(h.x, cf, acc.x);
        acc.y = fmaf(h.y, cf, acc.y);
    }
    for (int i = 32; i < cnt; i++) {           // rare: deg > 32
        int s = ep[i];
        float cf = rsqrtf(1.0f + (float)g_cur[s]) * dw;
        float2 h = __half22float2(Hh[(size_t)s * (COUTC / 2) + lane]);
        acc.x = fmaf(h.x, cf, acc.x);
        acc.y = fmaf(h.y, cf, acc.y);
    }

    int c = lane * 2;
    float2 hw = *reinterpret_cast<const float2*>(&g_H[(size_t)w * COUTC + c]);
    float d2 = dw * dw;
    float2 o;
    o.x = fmaf(hw.x, d2, acc.x);
    o.y = fmaf(hw.y, d2, acc.y);

    if (g_ovcnt == 0) {           // normal path: fused ReLU
        o.x = fmaxf(o.x, 0.0f);
        o.y = fmaxf(o.y, 0.0f);
    }
    *reinterpret_cast<float2*>(&out[(size_t)w * COUTC + c]) = o;
}

// ---------------- K3: overflow fixup (no-op when empty) ----------------
__global__ void __launch_bounds__(256) k_overflow(const int* __restrict__ src,
                                                  const int* __restrict__ dst,
                                                  float* __restrict__ out) {
    int total = g_ovcnt;
    for (int i = blockIdx.x * blockDim.x + threadIdx.x; i < total;
         i += gridDim.x * blockDim.x) {
        int e = g_ov[i];
        int s = src[e], d = dst[e];
        float cf = rsqrtf(1.0f + (float)g_cur[s]) * rsqrtf(1.0f + (float)g_cur[d]);
        const float* hp = &g_H[(size_t)s * COUTC];
        float* op = &out[(size_t)d * COUTC];
#pragma unroll
        for (int ch = 0; ch < COUTC; ch++) atomicAdd(&op[ch], hp[ch] * cf);
    }
}

// ---------------- K4: deferred ReLU (no-op when empty) ----------------
__global__ void __launch_bounds__(256) k_relufix(float* __restrict__ out, int total) {
    if (g_ovcnt == 0) return;
    for (int i = blockIdx.x * blockDim.x + threadIdx.x; i < total;
         i += gridDim.x * blockDim.x) {
        out[i] = fmaxf(out[i], 0.0f);
    }
}

// ---------------- K5: cleanup — restore the all-zero invariant for the next launch ----------------
__global__ void __launch_bounds__(256) k_cleanup(int n) {
    int i = blockIdx.x * blockDim.x + threadIdx.x;
    if (i < n) g_cur[i] = 0;
    if (i == 0) g_ovcnt = 0;
}

// ---------------- launch ----------------
extern "C" void kernel_launch(void* const* d_in, const int* in_sizes, int n_in,
                              void* d_out, int out_size) {
    const float* X   = (const float*)d_in[0];
    const float* W   = (const float*)d_in[1];
    const float* b   = (const float*)d_in[2];
    const int*   src = (const int*)d_in[3];
    const int*   dst = (const int*)d_in[4];
    float* out = (float*)d_out;

    int N = in_sizes[0] / CINC;
    int E = in_sizes[3];

    int gemmBlocks    = (N + 63) / 64;
    int scatterBlocks = (E + 255) / 256;

    k_fused<<<gemmBlocks + scatterBlocks, 256>>>(X, W, b, src, dst, N, E, gemmBlocks);
    k_gather<<<(int)(((long long)N * 32 + 255) / 256), 256>>>(out, N);
    k_overflow<<<148, 256>>>(src, dst, out);
    k_relufix<<<296, 256>>>(out, N * COUTC);
    k_cleanup<<<(N + 255) / 256, 256>>>(N);
}